// round 9
// baseline (speedup 1.0000x reference)
#include <cuda_runtime.h>
#include <cuda_bf16.h>
#include <math.h>

// PyramidROIAlign: B=2, N=1000, C=256, pool 7x7, levels 2..5 with
// H,W = 256,128,64,32.  Output: (B,N,7,7,C) float32.
//
// Mapping: one block per ROI, 512 threads = 16 warps. Warp pair (w>>1) owns
// pool pixels p = (w>>1), +8, ... ; bit w&1 selects the channel half
// (quads lane vs lane+32). Corner addresses are warp-uniform; each warp
// issues 4 independent LDG.128 per pixel while holding only 16 data regs,
// so occupancy stays high (48 warps/SM at <=42 regs) AND MLP is deep.

#define POOLP 7
#define NPIX  (POOLP * POOLP)   // 49

__global__ __launch_bounds__(512, 3)
void pyramid_roi_align_kernel(const float* __restrict__ boxes,
                              const float* __restrict__ meta,
                              const float* __restrict__ f2,
                              const float* __restrict__ f3,
                              const float* __restrict__ f4,
                              const float* __restrict__ f5,
                              float* __restrict__ out,
                              int B, int N)
{
    const int roi = blockIdx.x;            // 0 .. B*N-1
    const int b   = roi / N;

    // ---- per-ROI scalars (warp-uniform, cheap) ----
    const float y1 = boxes[roi * 4 + 0];
    const float x1 = boxes[roi * 4 + 1];
    const float y2 = boxes[roi * 4 + 2];
    const float x2 = boxes[roi * 4 + 3];
    const float h  = y2 - y1;
    const float w  = x2 - x1;

    const float image_area = meta[4] * meta[5];          // image_meta[0,4]*[0,5]
    const float lvl = log2f(sqrtf(h * w) / (224.0f / sqrtf(image_area)));
    float rl = 4.0f + rintf(lvl);                        // jnp.round == rint
    rl = fminf(fmaxf(rl, 2.0f), 5.0f);
    const int level = (int)rl;

    const float* fm;
    int H;
    switch (level) {
        case 2:  fm = f2; H = 256; break;
        case 3:  fm = f3; H = 128; break;
        case 4:  fm = f4; H = 64;  break;
        default: fm = f5; H = 32;  break;
    }
    const int W  = H;
    const int C4 = 64;                                   // 256 ch / 4

    const float4* __restrict__ fb =
        (const float4*)fm + (size_t)b * H * W * C4;
    float4* __restrict__ o4 =
        (float4*)out + (size_t)roi * NPIX * C4;

    const float Hm1 = (float)(H - 1);
    const float Wm1 = (float)(W - 1);
    const float sy  = h * Hm1 * (1.0f / (POOLP - 1));    // (y2-y1)*(H-1)/(ph-1)
    const float sx  = w * Wm1 * (1.0f / (POOLP - 1));
    const float by  = y1 * Hm1;
    const float bx  = x1 * Wm1;

    const int lane = threadIdx.x & 31;
    const int wrp  = threadIdx.x >> 5;                   // 0..15
    const int cq   = lane + ((wrp & 1) << 5);            // channel quad 0..63
    const int p0   = wrp >> 1;                           // pixel start 0..7

    for (int p = p0; p < NPIX; p += 8) {
        const int iy = p / POOLP;                        // const-div -> mul
        const int ix = p - iy * POOLP;

        // ---- sample coordinates (exact reference semantics) ----
        const float ys  = by + (float)iy * sy;
        const float xs  = bx + (float)ix * sx;
        const float y0f = floorf(ys);
        const float x0f = floorf(xs);
        int y0 = (int)y0f;  y0 = min(max(y0, 0), H - 1);
        int x0 = (int)x0f;  x0 = min(max(x0, 0), W - 1);
        const int y1i = min(y0 + 1, H - 1);
        const int x1i = min(x0 + 1, W - 1);
        const float fy = ys - y0f;                       // frac from UNclipped floor
        const float fx = xs - x0f;

        // warp-uniform corner base offsets (in float4 units)
        const int off_tl = (y0  * W + x0 ) * C4;
        const int off_tr = (y0  * W + x1i) * C4;
        const int off_bl = (y1i * W + x0 ) * C4;
        const int off_br = (y1i * W + x1i) * C4;

        // 4 independent LDG.128
        const float4 tl = fb[off_tl + cq];
        const float4 tr = fb[off_tr + cq];
        const float4 bl = fb[off_bl + cq];
        const float4 br = fb[off_br + cq];

        float4 r;
        {
            float t, bo;
            t = tl.x + (tr.x - tl.x) * fx;  bo = bl.x + (br.x - bl.x) * fx;  r.x = t + (bo - t) * fy;
            t = tl.y + (tr.y - tl.y) * fx;  bo = bl.y + (br.y - bl.y) * fx;  r.y = t + (bo - t) * fy;
            t = tl.z + (tr.z - tl.z) * fx;  bo = bl.z + (br.z - bl.z) * fx;  r.z = t + (bo - t) * fy;
            t = tl.w + (tr.w - tl.w) * fx;  bo = bl.w + (br.w - bl.w) * fx;  r.w = t + (bo - t) * fy;
        }
        o4[p * C4 + cq] = r;
    }
}

extern "C" void kernel_launch(void* const* d_in, const int* in_sizes, int n_in,
                              void* d_out, int out_size)
{
    const float* boxes = (const float*)d_in[0];
    const float* meta  = (const float*)d_in[1];
    const float* f2    = (const float*)d_in[2];
    const float* f3    = (const float*)d_in[3];
    const float* f4    = (const float*)d_in[4];
    const float* f5    = (const float*)d_in[5];
    float* out = (float*)d_out;

    const int B = in_sizes[1] / 14;            // image_meta is (B,14)
    const int N = in_sizes[0] / (4 * B);       // boxes is (B,N,4)

    pyramid_roi_align_kernel<<<B * N, 512>>>(boxes, meta, f2, f3, f4, f5,
                                             out, B, N);
}